// round 5
// baseline (speedup 1.0000x reference)
#include <cuda_runtime.h>

// TrueHigherOrderAttention — degenerate-mask reduction.
// The reference mask forces j==i and k==i, so the (j,k) softmax is an exact
// one-hot at (i,i,i):   out = ((x @ Wv1^T) .* (x @ Wv2^T)) @ Wc^T
//
// R5: two launches only. 512-thread CTAs with 4-way in-CTA K-split
// (16 warps/SM), full-K tiles staged once in dynamic smem, row-major layout
// with XOR-swizzled 16B granules => coalesced LDG, conflict-free STS and
// conflict-free LDS.128 compute loads. Scalar FFMA, 64 FFMA : 10 LDS per
// 4-k step. Smem-tree merge epilogue (no global partials, no reduce kernels).

constexpr int T  = 256;
constexpr int C  = 512;
constexpr int K  = 512;     // == C
constexpr int QK = K / 4;   // 128 k per quarter
constexpr int TILE_F = 32 * K;   // floats per staged tile (32 rows x 512)

__device__ float g_tmp[T * C];

// Swizzled float-index of (row, granule g) ; granule = 4 consecutive k floats.
__device__ __forceinline__ int swz(int row, int g)
{
    return row * K + ((g ^ (row & 7)) << 2);
}

// OUT = (X @ W1^T) [ .* (X @ W2^T) if DUAL ]   on a 32x32 tile.
// X: [M x C] row-major; W: [C x C] row-major (output col n = row n of W).
template <bool DUAL>
__global__ __launch_bounds__(512)
void gemm_kernel(const float* __restrict__ X,
                 const float* __restrict__ W1,
                 const float* __restrict__ W2,
                 float* __restrict__ OUT)
{
    extern __shared__ float sm[];
    float* xs  = sm;                    // [32][512] swizzled
    float* w1s = sm + TILE_F;           // [32][512] swizzled
    float* w2s = sm + 2 * TILE_F;       // DUAL only

    const int i0  = blockIdx.x * 32;
    const int n0  = blockIdx.y * 32;
    const int tid = threadIdx.x;

    // ---- Load phase: coalesced LDG.128, swizzled conflict-free STS.128 ----
    {
        const int row = tid >> 4;            // 0..31
        const int g0  = tid & 15;            // granule within 16-group
        const int xm  = row & 7;
#pragma unroll
        for (int it = 0; it < 8; it++) {
            const int g   = g0 + 16 * it;    // 0..127
            const int off = row * K + ((g ^ xm) << 2);
            const float4 xv = *(const float4*)&X [(i0 + row) * C + 4 * g];
            const float4 wv = *(const float4*)&W1[(n0 + row) * C + 4 * g];
            *(float4*)&xs [off] = xv;
            *(float4*)&w1s[off] = wv;
            if (DUAL) {
                const float4 uv = *(const float4*)&W2[(n0 + row) * C + 4 * g];
                *(float4*)&w2s[off] = uv;
            }
        }
    }
    __syncthreads();

    // ---- Compute phase: quarter qz covers k-granules [qz*32, qz*32+32) ----
    const int qz   = tid >> 7;               // 0..3
    const int htid = tid & 127;
    const int tx   = htid & 7;               // cols 4tx .. 4tx+3
    const int ty   = htid >> 3;              // rows 2ty, 2ty+1

    const int r0 = 2 * ty, r1 = r0 + 1;
    const int ba0 = r0 * K, ma0 = r0 & 7;
    const int ba1 = r1 * K, ma1 = r1 & 7;
    int bb[4], mb[4];
#pragma unroll
    for (int c = 0; c < 4; c++) {
        const int n = 4 * tx + c;
        bb[c] = n * K;
        mb[c] = n & 7;
    }

    float p[2][4] = {}, q[2][4] = {};

    const int gb = qz * 32;
#pragma unroll 2
    for (int gg = 0; gg < 32; gg++) {
        const int g = gb + gg;
        const float4 a0 = *(const float4*)&xs[ba0 + ((g ^ ma0) << 2)];
        const float4 a1 = *(const float4*)&xs[ba1 + ((g ^ ma1) << 2)];
#pragma unroll
        for (int c = 0; c < 4; c++) {
            const float4 b1 = *(const float4*)&w1s[bb[c] + ((g ^ mb[c]) << 2)];
            p[0][c] += a0.x * b1.x;  p[0][c] += a0.y * b1.y;
            p[0][c] += a0.z * b1.z;  p[0][c] += a0.w * b1.w;
            p[1][c] += a1.x * b1.x;  p[1][c] += a1.y * b1.y;
            p[1][c] += a1.z * b1.z;  p[1][c] += a1.w * b1.w;
            if (DUAL) {
                const float4 b2 = *(const float4*)&w2s[bb[c] + ((g ^ mb[c]) << 2)];
                q[0][c] += a0.x * b2.x;  q[0][c] += a0.y * b2.y;
                q[0][c] += a0.z * b2.z;  q[0][c] += a0.w * b2.w;
                q[1][c] += a1.x * b2.x;  q[1][c] += a1.y * b2.y;
                q[1][c] += a1.z * b2.z;  q[1][c] += a1.w * b2.w;
            }
        }
    }

    // ---- Merge quarters via smem (reuse xs region; all reads are done) ----
    __syncthreads();
    float4* red = (float4*)sm;               // planes of 384 float4
    if (qz != 0) {
        const int e = (qz - 1) * 128 + htid;
        red[0 * 384 + e] = make_float4(p[0][0], p[0][1], p[0][2], p[0][3]);
        red[1 * 384 + e] = make_float4(p[1][0], p[1][1], p[1][2], p[1][3]);
        if (DUAL) {
            red[2 * 384 + e] = make_float4(q[0][0], q[0][1], q[0][2], q[0][3]);
            red[3 * 384 + e] = make_float4(q[1][0], q[1][1], q[1][2], q[1][3]);
        }
    }
    __syncthreads();
    if (qz == 0) {
        float4 P0 = make_float4(p[0][0], p[0][1], p[0][2], p[0][3]);
        float4 P1 = make_float4(p[1][0], p[1][1], p[1][2], p[1][3]);
        float4 Q0, Q1;
        if (DUAL) {
            Q0 = make_float4(q[0][0], q[0][1], q[0][2], q[0][3]);
            Q1 = make_float4(q[1][0], q[1][1], q[1][2], q[1][3]);
        }
#pragma unroll
        for (int s = 0; s < 3; s++) {
            const int e = s * 128 + htid;
            const float4 u0 = red[0 * 384 + e];
            const float4 u1 = red[1 * 384 + e];
            P0.x += u0.x; P0.y += u0.y; P0.z += u0.z; P0.w += u0.w;
            P1.x += u1.x; P1.y += u1.y; P1.z += u1.z; P1.w += u1.w;
            if (DUAL) {
                const float4 v0 = red[2 * 384 + e];
                const float4 v1 = red[3 * 384 + e];
                Q0.x += v0.x; Q0.y += v0.y; Q0.z += v0.z; Q0.w += v0.w;
                Q1.x += v1.x; Q1.y += v1.y; Q1.z += v1.z; Q1.w += v1.w;
            }
        }
        float4 o0 = P0, o1 = P1;
        if (DUAL) {
            o0 = make_float4(P0.x * Q0.x, P0.y * Q0.y, P0.z * Q0.z, P0.w * Q0.w);
            o1 = make_float4(P1.x * Q1.x, P1.y * Q1.y, P1.z * Q1.z, P1.w * Q1.w);
        }
        *(float4*)&OUT[(i0 + r0) * C + n0 + 4 * tx] = o0;
        *(float4*)&OUT[(i0 + r1) * C + n0 + 4 * tx] = o1;
    }
}

extern "C" void kernel_launch(void* const* d_in, const int* in_sizes, int n_in,
                              void* d_out, int out_size)
{
    // metadata order: x, Wq, Wk1, Wk2, Wv1, Wv2, Wc
    const float* x   = (const float*)d_in[0];
    const float* Wv1 = (const float*)d_in[4];
    const float* Wv2 = (const float*)d_in[5];
    const float* Wc  = (const float*)d_in[6];
    float* out = (float*)d_out;

    float* tmp = nullptr;
    cudaGetSymbolAddress((void**)&tmp, g_tmp);

    const size_t sm1 = 3 * TILE_F * sizeof(float);   // 192 KB
    const size_t sm2 = 2 * TILE_F * sizeof(float);   // 128 KB
    cudaFuncSetAttribute(gemm_kernel<true>,
                         cudaFuncAttributeMaxDynamicSharedMemorySize, (int)sm1);
    cudaFuncSetAttribute(gemm_kernel<false>,
                         cudaFuncAttributeMaxDynamicSharedMemorySize, (int)sm2);

    dim3 grid(T / 32, C / 32);   // 8 x 16 = 128 CTAs
    gemm_kernel<true ><<<grid, 512, sm1>>>(x,   Wv1, Wv2,     tmp);
    gemm_kernel<false><<<grid, 512, sm2>>>(tmp, Wc,  nullptr, out);
}

// round 6
// speedup vs baseline: 4.5248x; 4.5248x over previous
#include <cuda_runtime.h>
#include <cstdint>

// TrueHigherOrderAttention — degenerate-mask reduction.
// The reference mask forces j==i and k==i, so the (j,k) softmax is an exact
// one-hot at (i,i,i):   out = ((x @ Wv1^T) .* (x @ Wv2^T)) @ Wc^T
//
// R6: warp-level tf32 mma.sync (m16n8k8) with 3xTF32 precision decomposition
// (a = a_hi + a_lo split at smem-store time; D = Ah*Bh + Ah*Bl + Al*Bh),
// fp32 accumulate. 32x32 CTA tile, 8 warps as 2(m) x 4(n), full-K per warp,
// KC=64 chunks with register prefetch. Smem: k-step blocks padded to 258
// words -> conflict-free STS (bank = lane + 2cc) and clean LDS.64 frag loads.

constexpr int T    = 256;
constexpr int C    = 512;
constexpr int KDIM = 512;
constexpr int KC   = 64;
constexpr int NCH  = KDIM / KC;   // 8
constexpr int BLK  = 258;         // padded words per k-step block
constexpr int TIER = 8 * BLK;     // hi -> lo offset (one tile tier)

// word offsets in dynamic smem
constexpr int A_HI  = 0;
constexpr int B1_HI = 2 * TIER;
constexpr int B2_HI = 4 * TIER;

__device__ float g_tmp[T * C];

__device__ __forceinline__ uint32_t f2tf32(float x)
{
    uint32_t r;
    asm("cvt.rna.tf32.f32 %0, %1;" : "=r"(r) : "f"(x));
    return r;
}

__device__ __forceinline__ void mma8(float* d, const uint32_t* a, const uint32_t* b)
{
    asm("mma.sync.aligned.m16n8k8.row.col.f32.tf32.tf32.f32 "
        "{%0,%1,%2,%3}, {%4,%5,%6,%7}, {%8,%9}, {%0,%1,%2,%3};"
        : "+f"(d[0]), "+f"(d[1]), "+f"(d[2]), "+f"(d[3])
        : "r"(a[0]), "r"(a[1]), "r"(a[2]), "r"(a[3]),
          "r"(b[0]), "r"(b[1]));
}

// OUT = (X @ W1^T) [ .* (X @ W2^T) if DUAL ]  on a 32x32 tile.
// X: [M x C] row-major; W: [C x C] row-major (output col n = row n of W).
template <bool DUAL>
__global__ __launch_bounds__(256)
void gemm_mma_kernel(const float* __restrict__ X,
                     const float* __restrict__ W1,
                     const float* __restrict__ W2,
                     float* __restrict__ OUT)
{
    extern __shared__ uint32_t sm[];

    const int i0   = blockIdx.x * 32;
    const int n0   = blockIdx.y * 32;
    const int tid  = threadIdx.x;
    const int lane = tid & 31;
    const int wid  = tid >> 5;

    // ---- loader mapping: row = tid>>3 (32 rows), float4 j = tid&7 and +8 ----
    const int lrow = tid >> 3;
    const int j0   = tid & 7;

    float4 xr[2], w1r[2], w2r[2];
    auto gload = [&](int kb) {
#pragma unroll
        for (int it = 0; it < 2; it++) {
            const int j = j0 + 8 * it;
            xr [it] = *(const float4*)&X [(i0 + lrow) * C + kb + 4 * j];
            w1r[it] = *(const float4*)&W1[(n0 + lrow) * C + kb + 4 * j];
            if (DUAL)
                w2r[it] = *(const float4*)&W2[(n0 + lrow) * C + kb + 4 * j];
        }
    };
    gload(0);

    // Store one float4 into tile 'hibase' at (row lrow, float4 j), splitting
    // each element into tf32 hi (rounded) and fp32 lo residual (truncated by
    // the MMA itself). Physical k position: p = 2*(k&3) + (k>>2) so that the
    // fragment pairs (k, k+4) are adjacent words -> LDS.64 frag loads.
    auto stile = [&](int hibase, const float4& v, int j) {
        uint32_t* dst = &sm[hibase + (j >> 1) * BLK + lrow * 8 + (j & 1)];
        const float vv[4] = {v.x, v.y, v.z, v.w};
#pragma unroll
        for (int cc = 0; cc < 4; cc++) {
            const uint32_t hi = f2tf32(vv[cc]);
            const float    lo = vv[cc] - __uint_as_float(hi);
            dst[2 * cc]        = hi;
            dst[TIER + 2 * cc] = __float_as_uint(lo);
        }
    };

    // ---- compute mapping: 8 warps = 2(m) x 4(n); warp tile m16 x n8 ----
    const int M0 = (wid >> 2) * 16;
    const int N0 = (wid & 3) * 8;
    const int ar = (M0 + (lane >> 2)) * 8 + 2 * (lane & 3);
    const int br = (N0 + (lane >> 2)) * 8 + 2 * (lane & 3);

    float p[3][4] = {}, q[3][4] = {};

    for (int ch = 0; ch < NCH; ch++) {
        if (ch) __syncthreads();
#pragma unroll
        for (int it = 0; it < 2; it++) {
            const int j = j0 + 8 * it;
            stile(A_HI,  xr [it], j);
            stile(B1_HI, w1r[it], j);
            if (DUAL) stile(B2_HI, w2r[it], j);
        }
        __syncthreads();
        if (ch + 1 < NCH) gload((ch + 1) * KC);   // prefetch under compute

#pragma unroll
        for (int s = 0; s < 8; s++) {
            const int o = s * BLK;
            const uint2 h02 = *(const uint2*)&sm[A_HI + o + ar];
            const uint2 h13 = *(const uint2*)&sm[A_HI + o + ar + 64];
            const uint2 l02 = *(const uint2*)&sm[A_HI + TIER + o + ar];
            const uint2 l13 = *(const uint2*)&sm[A_HI + TIER + o + ar + 64];
            const uint32_t Ah[4] = {h02.x, h13.x, h02.y, h13.y};
            const uint32_t Al[4] = {l02.x, l13.x, l02.y, l13.y};

            const uint2 b1h = *(const uint2*)&sm[B1_HI + o + br];
            const uint2 b1l = *(const uint2*)&sm[B1_HI + TIER + o + br];
            const uint32_t B1h[2] = {b1h.x, b1h.y};
            const uint32_t B1l[2] = {b1l.x, b1l.y};

            mma8(p[0], Ah, B1h);
            mma8(p[1], Ah, B1l);
            mma8(p[2], Al, B1h);

            if (DUAL) {
                const uint2 b2h = *(const uint2*)&sm[B2_HI + o + br];
                const uint2 b2l = *(const uint2*)&sm[B2_HI + TIER + o + br];
                const uint32_t B2h[2] = {b2h.x, b2h.y};
                const uint32_t B2l[2] = {b2l.x, b2l.y};
                mma8(q[0], Ah, B2h);
                mma8(q[1], Ah, B2l);
                mma8(q[2], Al, B2h);
            }
        }
    }

    // ---- epilogue: merge decomposition terms, (optional) product, store ----
    float P[4], Q[4];
#pragma unroll
    for (int i = 0; i < 4; i++) {
        P[i] = p[0][i] + p[1][i] + p[2][i];
        if (DUAL) Q[i] = q[0][i] + q[1][i] + q[2][i];
    }
    const int row = i0 + M0 + (lane >> 2);
    const int col = n0 + N0 + 2 * (lane & 3);
    float2 v0, v1;
    if (DUAL) {
        v0 = make_float2(P[0] * Q[0], P[1] * Q[1]);
        v1 = make_float2(P[2] * Q[2], P[3] * Q[3]);
    } else {
        v0 = make_float2(P[0], P[1]);
        v1 = make_float2(P[2], P[3]);
    }
    *(float2*)&OUT[ row      * C + col] = v0;
    *(float2*)&OUT[(row + 8) * C + col] = v1;
}

extern "C" void kernel_launch(void* const* d_in, const int* in_sizes, int n_in,
                              void* d_out, int out_size)
{
    // metadata order: x, Wq, Wk1, Wk2, Wv1, Wv2, Wc
    const float* x   = (const float*)d_in[0];
    const float* Wv1 = (const float*)d_in[4];
    const float* Wv2 = (const float*)d_in[5];
    const float* Wc  = (const float*)d_in[6];
    float* out = (float*)d_out;

    float* tmp = nullptr;
    cudaGetSymbolAddress((void**)&tmp, g_tmp);

    const int sm1 = 6 * TIER * 4;   // 49536 B
    const int sm2 = 4 * TIER * 4;   // 33024 B
    cudaFuncSetAttribute(gemm_mma_kernel<true>,
                         cudaFuncAttributeMaxDynamicSharedMemorySize, sm1);
    cudaFuncSetAttribute(gemm_mma_kernel<false>,
                         cudaFuncAttributeMaxDynamicSharedMemorySize, sm2);

    dim3 grid(T / 32, C / 32);   // 8 x 16 = 128 CTAs
    gemm_mma_kernel<true ><<<grid, 256, sm1>>>(x,   Wv1, Wv2,     tmp);
    gemm_mma_kernel<false><<<grid, 256, sm2>>>(tmp, Wc,  nullptr, out);
}